// round 3
// baseline (speedup 1.0000x reference)
#include <cuda_runtime.h>
#include <math.h>

// TopKRouter: logits = x @ gate_w^T, softmax, top-2 (+renorm), aux loss.
// T=16384, D=2048, E=64, K=2.
// Output (float32): [indices(2T) | weights(2T) | ... | aux at out_size-1]
//
// R1 137us: LDS-bound (model-exact). R2 161us: 8 warps -> latency-bound.
// R3: 512 thr (16 warps), thread tile 4tok x 4exp, W duplicated in smem so
// LDS.128 yields broadcast f32x2 directly (no pack MOVs). Warp = 8tg x 4eg
// -> 3 LDS wavefronts/warp/k. FMA-pipe bound at 64 cyc/SM/k.

#define NEXP   64
#define TOPK   2
#define BK     16
#define MT     128
#define NTHR   512
#define MAXBLK 512

__device__ int   g_counts[NEXP];
__device__ float g_wsum_part[MAXBLK * NEXP];
__device__ float g_z_part[MAXBLK];

__device__ __forceinline__ void ffma2(unsigned long long &d,
                                      unsigned long long a,
                                      unsigned long long b) {
    asm("fma.rn.f32x2 %0, %1, %2, %0;" : "+l"(d) : "l"(a), "l"(b));
}
__device__ __forceinline__ void unpack2(unsigned long long v, float &lo, float &hi) {
    unsigned int l, h;
    asm("mov.b64 {%0, %1}, %2;" : "=r"(l), "=r"(h) : "l"(v));
    lo = __uint_as_float(l);
    hi = __uint_as_float(h);
}

__global__ __launch_bounds__(NTHR, 1)
void router_main(const float* __restrict__ X, const float* __restrict__ W,
                 float* __restrict__ out, int T, int D)
{
    // GEMM phase: xs[2][BK][128] (16KB) + wd[2][BK][128] dup (16KB) = 32KB
    // Epilogue overlay: 128*65 + 128 + 128 + 64 + 512 floats = ~36.6KB
    __shared__ __align__(16) float smem_f[9216];
    float* xs = smem_f;          // [2][BK][MT]
    float* wd = smem_f + 4096;   // [2][BK][2*NEXP] duplicated

    const int tid  = threadIdx.x;
    const int lane = tid & 31;
    const int wrp  = tid >> 5;
    const int tg   = (lane & 7) | ((wrp & 3) << 3);   // 0..31
    const int eg   = (lane >> 3) | ((wrp >> 2) << 2); // 0..15
    const int t0   = tg * 4;
    const int e0   = eg * 4;
    const long tokBase = (long)blockIdx.x * MT;
    const int NC = D / BK;

    // staging indices
    const int lrow = tid >> 2;        // 0..127 (x rows); 0..63 for w (tid<256)
    const int c4   = tid & 3;         // float4 col in BK
    const int swS  = c4 << 2;

    unsigned long long acc[2][4];
#pragma unroll
    for (int p = 0; p < 2; p++)
#pragma unroll
        for (int j = 0; j < 4; j++) acc[p][j] = 0ull;

    const float* Xb = X + tokBase * D;
    float4 xreg, wreg;

    // ---- prologue: chunk 0 ----
    xreg = *(const float4*)(Xb + (long)lrow * D + c4 * 4);
    if (tid < 256) wreg = *(const float4*)(W + (long)lrow * D + c4 * 4);
    {
        int col = lrow ^ swS;
#pragma unroll
        for (int j = 0; j < 4; j++)
            xs[(c4 * 4 + j) * MT + col] = ((const float*)&xreg)[j];
        if (tid < 256) {
#pragma unroll
            for (int j = 0; j < 4; j++) {
                float v = ((const float*)&wreg)[j];
                *(float2*)(wd + (c4 * 4 + j) * (2 * NEXP) + 2 * col) =
                    make_float2(v, v);
            }
        }
    }
    __syncthreads();

    // ---- main loop, double buffered ----
    for (int c = 0; c < NC; ++c) {
        if (c + 1 < NC) {
            xreg = *(const float4*)(Xb + (long)lrow * D + (c + 1) * BK + c4 * 4);
            if (tid < 256)
                wreg = *(const float4*)(W + (long)lrow * D + (c + 1) * BK + c4 * 4);
        }
        const float* xb = xs + (c & 1) * BK * MT;
        const float* wb = wd + (c & 1) * BK * (2 * NEXP);
#pragma unroll
        for (int k = 0; k < BK; k++) {
            const int sw = (k >> 2) << 2;
            ulonglong2 xa = *(const ulonglong2*)(xb + k * MT + (t0 ^ sw));
            ulonglong2 wa = *(const ulonglong2*)(wb + k * (2 * NEXP) + 2 * (e0 ^ sw));
            ulonglong2 wbq = *(const ulonglong2*)(wb + k * (2 * NEXP) + 2 * (e0 ^ sw) + 4);
            ffma2(acc[0][0], xa.x, wa.x);
            ffma2(acc[0][1], xa.x, wa.y);
            ffma2(acc[0][2], xa.x, wbq.x);
            ffma2(acc[0][3], xa.x, wbq.y);
            ffma2(acc[1][0], xa.y, wa.x);
            ffma2(acc[1][1], xa.y, wa.y);
            ffma2(acc[1][2], xa.y, wbq.x);
            ffma2(acc[1][3], xa.y, wbq.y);
        }
        if (c + 1 < NC) {
            float* xb2 = xs + ((c + 1) & 1) * BK * MT;
            float* wb2 = wd + ((c + 1) & 1) * BK * (2 * NEXP);
            int col = lrow ^ swS;
#pragma unroll
            for (int j = 0; j < 4; j++)
                xb2[(c4 * 4 + j) * MT + col] = ((const float*)&xreg)[j];
            if (tid < 256) {
#pragma unroll
                for (int j = 0; j < 4; j++) {
                    float v = ((const float*)&wreg)[j];
                    *(float2*)(wb2 + (c4 * 4 + j) * (2 * NEXP) + 2 * col) =
                        make_float2(v, v);
                }
            }
        }
        __syncthreads();
    }

    // ---- epilogue: overlay smem ----
    float* lg       = smem_f;                    // [MT][65]
    float* invden_s = smem_f + MT * 65;          // [MT]
    float* zs       = invden_s + MT;             // [MT]
    int*   hist     = (int*)(zs + MT);           // [NEXP]
    float* colred   = (float*)(hist + NEXP);     // [8][NEXP]

#pragma unroll
    for (int p = 0; p < 2; p++)
#pragma unroll
        for (int j = 0; j < 4; j++) {
            float lo, hi;
            unpack2(acc[p][j], lo, hi);
            lg[(t0 + 2 * p    ) * 65 + e0 + j] = lo;
            lg[(t0 + 2 * p + 1) * 65 + e0 + j] = hi;
        }
    if (tid < NEXP) hist[tid] = 0;
    __syncthreads();

    if (tid < MT) {
        const int t = tid;
        float* row = lg + t * 65;
        // top-2 on RAW logits (exact fp32 compares, monotone w.r.t. softmax)
        float b0 = row[0], b1 = -3.0e38f;
        int   i0 = 0,      i1 = 0;
#pragma unroll 8
        for (int e = 1; e < NEXP; e++) {
            float v = row[e];
            if (v > b0) { b1 = b0; i1 = i0; b0 = v; i0 = e; }
            else if (v > b1) { b1 = v; i1 = e; }
        }
        const float m = b0;
        float s = 0.f;
#pragma unroll 8
        for (int e = 0; e < NEXP; e++) {
            float v = __expf(row[e] - m);
            row[e] = v;
            s += v;
        }
        float v0 = row[i0];
        float v1 = row[i1];
        float st  = v0 + v1;
        float wn0 = __fdiv_rn(v0, st);
        float wn1 = __fdiv_rn(v1, st);
        long g = tokBase + t;
        out[2 * g]     = (float)i0;
        out[2 * g + 1] = (float)i1;
        out[2 * (long)T + 2 * g]     = wn0;
        out[2 * (long)T + 2 * g + 1] = wn1;
        invden_s[t] = __frcp_rn(s);
        float lse = m + logf(s);
        zs[t] = lse * lse;
        atomicAdd(&hist[i0], 1);
        atomicAdd(&hist[i1], 1);
    }
    __syncthreads();

    // per-block expert sums of softmax weights (deterministic order)
    {
        const int e   = tid & 63;
        const int seg = tid >> 6;  // 0..7
        float s = 0.f;
#pragma unroll 4
        for (int t = seg * 16; t < seg * 16 + 16; ++t)
            s += lg[t * 65 + e] * invden_s[t];
        colred[seg * NEXP + e] = s;
    }
    __syncthreads();
    if (tid < NEXP) {
        float p = 0.f;
#pragma unroll
        for (int sgi = 0; sgi < 8; ++sgi) p += colred[sgi * NEXP + tid];
        g_wsum_part[blockIdx.x * NEXP + tid] = p;
        atomicAdd(&g_counts[tid], hist[tid]);
        zs[tid] += zs[tid + 64];
    }
    __syncthreads();
    if (tid == 0) {
        float z = 0.f;
        for (int t = 0; t < 64; t++) z += zs[t];
        g_z_part[blockIdx.x] = z;
    }
}

__global__ void router_init() { g_counts[threadIdx.x] = 0; }

__global__ void router_finalize(float* __restrict__ out, int T, int nblk, int aux_pos)
{
    __shared__ float red[NEXP];
    const int e = threadIdx.x;
    float ws = 0.f;
    for (int b = 0; b < nblk; b++) ws += g_wsum_part[b * NEXP + e];
    float f = (float)g_counts[e] / (float)(T * TOPK);
    float P = ws / (float)T;
    red[e] = f * P;
    __syncthreads();
    if (e == 0) {
        float bal = 0.f;
        for (int i = 0; i < NEXP; i++) bal += red[i];
        bal *= (float)NEXP;
        float zsum = 0.f;
        for (int b = 0; b < nblk; b++) zsum += g_z_part[b];
        float z = zsum / (float)T;
        out[aux_pos] = 0.01f * bal + 0.001f * z;
    }
}

extern "C" void kernel_launch(void* const* d_in, const int* in_sizes, int n_in,
                              void* d_out, int out_size)
{
    const float* X = (const float*)d_in[0];
    const float* W = (const float*)d_in[1];
    float* out = (float*)d_out;

    const int D = in_sizes[1] / NEXP;     // 2048
    const int T = in_sizes[0] / D;        // 16384
    const int nblk = T / MT;              // 128

    router_init<<<1, NEXP>>>();
    router_main<<<nblk, NTHR>>>(X, W, out, T, D);
    router_finalize<<<1, NEXP>>>(out, T, nblk, out_size - 1);
}